// round 2
// baseline (speedup 1.0000x reference)
#include <cuda_runtime.h>
#include <math.h>

#define TT 2048
#define BB 8192
#define NTOT (TT * BB)          // 16777216
#define GAMMA 0.99f
#define NSEG 32
#define SEGLEN 64               // NSEG * SEGLEN == TT
#define MIN_VAR 1e-6
#define MIN_CLIP (-10.0f)
#define MAX_CLIP (10.0f)

__device__ double g_sum;
__device__ double g_sum2;
__device__ float  g_scale;
// [seg][field(7)][col] layout: coalesced writes in scan, coalesced reads in combine
__device__ float  g_tup[NSEG * 7 * BB];   // 7.34 MB scratch

__global__ void rr_zero_kernel() {
    g_sum = 0.0;
    g_sum2 = 0.0;
}

// Pure streaming scan: one thread per (column, segment).
// warp = 32 consecutive columns at one segment -> every access is one 128B line.
__global__ __launch_bounds__(256)
void rr_scan_kernel(const float* __restrict__ x,
                    const float* __restrict__ dn) {
    const int tid  = blockIdx.x * blockDim.x + threadIdx.x;
    const int lane = tid & 31;
    const int w    = tid >> 5;            // 0..8191
    const int seg  = w & (NSEG - 1);      // 0..31
    const int col  = ((w >> 5) << 5) + lane;  // 0..8191
    const int t0   = seg * SEGLEN;

    const float* __restrict__ xp  = x  + t0 * BB + col;
    const float* __restrict__ dpm = dn + t0 * BB + col;

    // d_prev for the first step of this segment
    float dp = (seg == 0) ? 0.0f : dpm[-BB];

    // Affine composition r_end = A*r0 + Bv ; segment sums as quadratic forms in r0
    float A = 1.0f, Bv = 0.0f;
    float Sa = 0.0f, Sb = 0.0f, Saa = 0.0f, Sab = 0.0f, Sbb = 0.0f;

#pragma unroll 8
    for (int i = 0; i < SEGLEN; i++) {
        float xv = xp[i * BB];
        float a  = GAMMA * (1.0f - dp);
        dp = dpm[i * BB];              // d_prev for next iteration
        A  = A * a;
        Bv = fmaf(a, Bv, xv);
        Sa += A;
        Sb += Bv;
        Saa = fmaf(A,  A,  Saa);
        Sab = fmaf(A,  Bv, Sab);
        Sbb = fmaf(Bv, Bv, Sbb);
    }

    float* tp = g_tup + (seg * 7) * BB + col;
    tp[0 * BB] = A;
    tp[1 * BB] = Bv;
    tp[2 * BB] = Sa;
    tp[3 * BB] = Sb;
    tp[4 * BB] = Saa;
    tp[5 * BB] = Sab;
    tp[6 * BB] = Sbb;
}

// Cross-segment combine: one thread per column (8192 threads).
// Scratch is L2-resident; per-column math in float (32 terms), reduction in double.
__global__ __launch_bounds__(256)
void rr_combine_kernel(const float* __restrict__ ret) {
    const int col = blockIdx.x * blockDim.x + threadIdx.x;

    float r0   = ret[col];
    float sum  = 0.0f;
    float sum2 = 0.0f;
#pragma unroll
    for (int s = 0; s < NSEG; s++) {
        const float* q = g_tup + (s * 7) * BB + col;
        float A   = q[0 * BB];
        float Bv  = q[1 * BB];
        float Sa  = q[2 * BB];
        float Sb  = q[3 * BB];
        float Saa = q[4 * BB];
        float Sab = q[5 * BB];
        float Sbb = q[6 * BB];
        sum  += fmaf(Sa, r0, Sb);
        sum2 += fmaf(fmaf(Saa, r0, 2.0f * Sab), r0, Sbb);
        r0 = fmaf(A, r0, Bv);
    }

    double dsum  = (double)sum;
    double dsum2 = (double)sum2;
#pragma unroll
    for (int off = 16; off > 0; off >>= 1) {
        dsum  += __shfl_down_sync(0xffffffffu, dsum,  off);
        dsum2 += __shfl_down_sync(0xffffffffu, dsum2, off);
    }

    __shared__ double s1[8], s2[8];
    const int lane = threadIdx.x & 31;
    const int wrp  = threadIdx.x >> 5;
    if (lane == 0) { s1[wrp] = dsum; s2[wrp] = dsum2; }
    __syncthreads();
    if (wrp == 0) {
        double a = (lane < 8) ? s1[lane] : 0.0;
        double b = (lane < 8) ? s2[lane] : 0.0;
#pragma unroll
        for (int off = 4; off > 0; off >>= 1) {
            a += __shfl_down_sync(0xffffffffu, a, off);
            b += __shfl_down_sync(0xffffffffu, b, off);
        }
        if (lane == 0) {
            atomicAdd(&g_sum,  a);
            atomicAdd(&g_sum2, b);
        }
    }
}

__global__ void rr_finalize_kernel(const float* __restrict__ mean_p,
                                   const float* __restrict__ var_p,
                                   const float* __restrict__ count_p) {
    const double N = (double)NTOT;
    double bm = g_sum / N;
    double bv = g_sum2 / N - bm * bm;
    if (bv < 0.0) bv = 0.0;

    double mean0  = (double)mean_p[0];
    double var0   = (double)var_p[0];
    double count0 = (double)count_p[0];

    double new_var;
    if (count0 == 0.0) {
        new_var = bv;
    } else {
        double delta = bm - mean0;
        double total = count0 + N;
        double m2 = var0 * count0 + bv * N + delta * delta * count0 * N / total;
        new_var = m2 / total;
    }
    double obs_var = new_var > MIN_VAR ? new_var : MIN_VAR;
    g_scale = (float)(1.0 / sqrt(obs_var));
}

__global__ __launch_bounds__(256)
void rr_norm_kernel(const float4* __restrict__ x4, float4* __restrict__ o4) {
    int i = blockIdx.x * blockDim.x + threadIdx.x;
    float s = g_scale;
    float4 v = x4[i];
    float4 r;
    r.x = fminf(MAX_CLIP, fmaxf(MIN_CLIP, v.x * s));
    r.y = fminf(MAX_CLIP, fmaxf(MIN_CLIP, v.y * s));
    r.z = fminf(MAX_CLIP, fmaxf(MIN_CLIP, v.z * s));
    r.w = fminf(MAX_CLIP, fmaxf(MIN_CLIP, v.w * s));
    o4[i] = r;
}

extern "C" void kernel_launch(void* const* d_in, const int* in_sizes, int n_in,
                              void* d_out, int out_size) {
    const float* x     = (const float*)d_in[0];
    const float* dones = (const float*)d_in[1];
    const float* ret   = (const float*)d_in[2];
    const float* mean  = (const float*)d_in[3];
    const float* var   = (const float*)d_in[4];
    const float* count = (const float*)d_in[5];
    float* out = (float*)d_out;

    rr_zero_kernel<<<1, 1>>>();
    rr_scan_kernel<<<(NSEG * BB) / 256, 256>>>(x, dones);
    rr_combine_kernel<<<BB / 256, 256>>>(ret);
    rr_finalize_kernel<<<1, 1>>>(mean, var, count);

    const int n4 = NTOT / 4;
    rr_norm_kernel<<<n4 / 256, 256>>>((const float4*)x, (float4*)out);
}